// round 3
// baseline (speedup 1.0000x reference)
#include <cuda_runtime.h>

#define NN 100000
#define NE 1600000
#define D 32
#define CUT_K 320000        // int(E * 0.2)
#define EQ_CAP 2048
#define NBLK 391            // ceil(NN/256) for the scan

// ---------------- device scratch (no allocations allowed) ----------------
__device__ __align__(16) float g_nh[NN * D];     // row-normalized h
__device__ __align__(16) float g_hs[NN * D];     // h * norm  (message payload)
__device__ __align__(16) float g_hnew[NN * D];   // aggregation target
__device__ unsigned g_pkey[NE];                  // cos keys, PERM (dst-sorted) order
__device__ int   g_psrc[NE];                     // src per perm slot
__device__ int   g_pe[NE];                       // original edge id per perm slot
__device__ int   g_iperm[NE];                    // edge id -> perm slot
__device__ int   g_rowstart[NN + 1];
__device__ int   g_cursor[NN];
__device__ int   g_bsum[NBLK];
__device__ float g_norm[NN];
__device__ int   g_deg[NN];
__device__ __align__(4) unsigned char g_eqflagP[NE];  // tie-drop flags, perm order
__device__ int   g_eq_list[EQ_CAP];              // perm slots with key == threshold
__device__ int   g_eq_count;
__device__ unsigned int g_hist[256];             // zero between rounds (resolve clears)
__device__ unsigned int g_prefix;
__device__ int   g_kremain;

// float -> order-preserving uint (ascending)
__device__ __forceinline__ unsigned f2o(float f) {
    unsigned u = __float_as_uint(f);
    return (u & 0x80000000u) ? ~u : (u | 0x80000000u);
}

// ================= one-time setup: degree, norm, CSR build =================
__global__ void k_deg_zero() {
    int i = blockIdx.x * blockDim.x + threadIdx.x;
    if (i < NN) g_deg[i] = 0;
}
__global__ void k_deg(const int* __restrict__ dst) {
    int i = blockIdx.x * blockDim.x + threadIdx.x;
    if (i < NE) atomicAdd(&g_deg[dst[i]], 1);
}
// per-256-chunk exclusive scan of deg; also compute norm
__global__ void k_scan1() {
    __shared__ int s[256];
    int t = threadIdx.x;
    int i = blockIdx.x * 256 + t;
    int v = (i < NN) ? g_deg[i] : 0;
    if (i < NN) {
        float d = (float)v;
        if (d < 1.0f) d = 1.0f;
        g_norm[i] = 1.0f / sqrtf(d);
    }
    s[t] = v;
    __syncthreads();
    #pragma unroll
    for (int o = 1; o < 256; o <<= 1) {
        int x = (t >= o) ? s[t - o] : 0;
        __syncthreads();
        s[t] += x;
        __syncthreads();
    }
    if (i < NN) g_rowstart[i] = s[t] - v;   // local exclusive
    if (t == 255) g_bsum[blockIdx.x] = s[255];
}
// exclusive scan of block sums (1 block)
__global__ void k_scan2() {
    __shared__ int s[512];
    int t = threadIdx.x;
    int v = (t < NBLK) ? g_bsum[t] : 0;
    s[t] = v;
    __syncthreads();
    #pragma unroll
    for (int o = 1; o < 512; o <<= 1) {
        int x = (t >= o) ? s[t - o] : 0;
        __syncthreads();
        s[t] += x;
        __syncthreads();
    }
    if (t < NBLK) g_bsum[t] = s[t] - v;     // exclusive
}
// add block offsets; init cursor; set rowstart[NN]
__global__ void k_scan3() {
    int i = blockIdx.x * blockDim.x + threadIdx.x;
    if (i < NN) {
        int r = g_rowstart[i] + g_bsum[i >> 8];
        g_rowstart[i] = r;
        g_cursor[i] = r;
    }
    if (i == 0) g_rowstart[NN] = NE;
}
// counting-sort edges by dst
__global__ void k_build(const int* __restrict__ src, const int* __restrict__ dst) {
    int e = blockIdx.x * blockDim.x + threadIdx.x;
    if (e >= NE) return;
    int d = dst[e];
    int pos = atomicAdd(&g_cursor[d], 1);
    g_psrc[pos] = src[e];
    g_pe[pos] = e;
    g_iperm[e] = pos;
}

// ======== per-hop prep: 8 lanes/row, float4. nh = h/max(||h||,eps); hs = h*norm
__global__ void k_prep(const float* __restrict__ feat, int hop) {
    int g = blockIdx.x * blockDim.x + threadIdx.x;
    int row = g >> 3, sub = g & 7;
    if (row >= NN) return;
    float nm = g_norm[row];
    const float4* hin4 = hop ? (const float4*)g_hnew : (const float4*)feat;
    float4 v = hin4[row * 8 + sub];
    if (hop) { v.x *= nm; v.y *= nm; v.z *= nm; v.w *= nm; }  // trailing norm, prev hop
    float ss = v.x * v.x + v.y * v.y + v.z * v.z + v.w * v.w;
    #pragma unroll
    for (int o = 4; o > 0; o >>= 1) ss += __shfl_xor_sync(0xFFFFFFFFu, ss, o);
    float inv = 1.0f / fmaxf(sqrtf(ss), 1e-12f);
    ((float4*)g_nh)[row * 8 + sub] = make_float4(v.x * inv, v.y * inv, v.z * inv, v.w * inv);
    ((float4*)g_hs)[row * 8 + sub] = make_float4(v.x * nm,  v.y * nm,  v.z * nm,  v.w * nm);
}

// ---------------- per-hop clear: eq flags + scalars (no h_new zeroing needed)
__global__ void k_hopclear() {
    int i = blockIdx.x * blockDim.x + threadIdx.x;
    if (i < NE / 16) ((uint4*)g_eqflagP)[i] = make_uint4(0u, 0u, 0u, 0u);
    if (i == 0) { g_eq_count = 0; g_prefix = 0u; g_kremain = CUT_K; }
}

// ------ cosine per edge (8 lanes/edge, float4) -> pkey[perm slot]; fused hist rnd 1
__global__ void k_cos(const int* __restrict__ src, const int* __restrict__ dst) {
    __shared__ unsigned sh[256];
    for (int i = threadIdx.x; i < 256; i += blockDim.x) sh[i] = 0u;
    __syncthreads();
    int g = blockIdx.x * blockDim.x + threadIdx.x;
    int e = g >> 3, sub = g & 7;
    float p = 0.0f;
    if (e < NE) {
        int s = src[e], d = dst[e];
        float4 a = ((const float4*)g_nh)[s * 8 + sub];
        float4 b = ((const float4*)g_nh)[d * 8 + sub];
        p = a.x * b.x + a.y * b.y + a.z * b.z + a.w * b.w;
    }
    #pragma unroll
    for (int o = 4; o > 0; o >>= 1) p += __shfl_xor_sync(0xFFFFFFFFu, p, o);
    if (e < NE && sub == 0) {
        unsigned key = f2o(p);
        g_pkey[g_iperm[e]] = key;
        atomicAdd(&sh[key >> 24], 1u);
    }
    __syncthreads();
    for (int i = threadIdx.x; i < 256; i += blockDim.x)
        if (sh[i]) atomicAdd(&g_hist[i], sh[i]);
}

// ---------------- radix select: histogram round (coalesced pkey reads)
__global__ void k_hist(int shift, unsigned mask) {
    __shared__ unsigned sh[256];
    for (int i = threadIdx.x; i < 256; i += blockDim.x) sh[i] = 0u;
    __syncthreads();
    unsigned pref = g_prefix;
    int stride = gridDim.x * blockDim.x;
    for (int e = blockIdx.x * blockDim.x + threadIdx.x; e < NE; e += stride) {
        unsigned key = g_pkey[e];
        if ((key & mask) == (pref & mask))
            atomicAdd(&sh[(key >> shift) & 255u], 1u);
    }
    __syncthreads();
    for (int i = threadIdx.x; i < 256; i += blockDim.x)
        if (sh[i]) atomicAdd(&g_hist[i], sh[i]);
}

// ---------------- radix select: resolve round (1 block) ----------------
__global__ void k_resolve(int shift) {
    __shared__ unsigned sh[256];
    int t = threadIdx.x;
    sh[t] = g_hist[t];
    __syncthreads();
    if (t == 0) {
        unsigned cum = 0;
        int kr = g_kremain;
        for (int b = 0; b < 256; b++) {
            unsigned c = sh[b];
            if (cum + c >= (unsigned)kr) {
                g_prefix |= ((unsigned)b) << shift;
                g_kremain = kr - (int)cum;
                break;
            }
            cum += c;
        }
    }
    g_hist[t] = 0u;   // restore invariant for next round / next hop
}

// -------- exact tie handling: rank equal-key edges by ORIGINAL edge index
__global__ void k_eq_gather() {
    int j = blockIdx.x * blockDim.x + threadIdx.x;
    if (j >= NE) return;
    if (g_pkey[j] == g_prefix) {
        int pos = atomicAdd(&g_eq_count, 1);
        if (pos < EQ_CAP) g_eq_list[pos] = j;     // perm slot
    }
}
__global__ void k_eq_mark() {
    int n = g_eq_count; if (n > EQ_CAP) n = EQ_CAP;
    int r = g_kremain;                 // how many of the equal-key edges to drop
    for (int i = threadIdx.x; i < n; i += blockDim.x) {
        int ji = g_eq_list[i];
        int ei = g_pe[ji];             // original edge index
        int rank = 0;
        for (int m = 0; m < n; m++) rank += (g_pe[g_eq_list[m]] < ei);
        if (rank < r) g_eqflagP[ji] = 1;  // drop the r lowest-orig-index ties
    }
}

// -------- pull aggregation: 8 lanes per node, register accumulate, no atomics
__global__ void k_agg() {
    int g = blockIdx.x * blockDim.x + threadIdx.x;
    int row = g >> 3, sub = g & 7;
    if (row >= NN) return;
    int beg = g_rowstart[row];
    int end = g_rowstart[row + 1];
    unsigned thr = g_prefix;
    float4 acc = make_float4(0.f, 0.f, 0.f, 0.f);
    for (int j = beg; j < end; j++) {
        unsigned pk = __ldg(&g_pkey[j]);
        bool keep = (pk > thr) || (pk == thr && g_eqflagP[j] == 0);
        if (keep) {
            int s = __ldg(&g_psrc[j]);
            float4 v = ((const float4*)g_hs)[s * 8 + sub];
            acc.x += v.x; acc.y += v.y; acc.z += v.z; acc.w += v.w;
        }
    }
    ((float4*)g_hnew)[row * 8 + sub] = acc;
}

// ---------------- final: out = (h_new * norm) @ W^T ----------------
__global__ void k_out(const float* __restrict__ W, float* __restrict__ out) {
    __shared__ float sW[32 * 33];
    for (int i = threadIdx.x; i < 1024; i += blockDim.x) {
        int o = i >> 5, k = i & 31;
        sW[o * 33 + k] = W[i];
    }
    __syncthreads();
    int g = blockIdx.x * blockDim.x + threadIdx.x;
    int row = g >> 5, lane = g & 31;
    if (row >= NN) return;
    float hv = g_hnew[row * D + lane] * g_norm[row];
    float acc = 0.0f;
    #pragma unroll
    for (int k = 0; k < 32; k++) {
        float hk = __shfl_sync(0xFFFFFFFFu, hv, k);
        acc += hk * sW[lane * 33 + k];
    }
    out[row * D + lane] = acc;
}

extern "C" void kernel_launch(void* const* d_in, const int* in_sizes, int n_in,
                              void* d_out, int out_size) {
    const float* feat = (const float*)d_in[0];
    const float* W    = (const float*)d_in[1];
    const int*   src  = (const int*)d_in[2];
    const int*   dst  = (const int*)d_in[3];
    float* out = (float*)d_out;

    const int TB = 256;
    const int grid_node  = (NN + TB - 1) / TB;
    const int grid_edge  = (NE + TB - 1) / TB;
    const int grid_row8  = (NN * 8 + TB - 1) / TB;
    const int grid_edge8 = (NE * 8 + TB - 1) / TB;
    const int grid_rowW  = (NN * 32 + TB - 1) / TB;
    const int grid_clear = (NE / 16 + TB - 1) / TB;

    // one-time CSR build (dst is loop-invariant)
    k_deg_zero<<<grid_node, TB>>>();
    k_deg<<<grid_edge, TB>>>(dst);
    k_scan1<<<NBLK, 256>>>();
    k_scan2<<<1, 512>>>();
    k_scan3<<<grid_node, TB>>>();
    k_build<<<grid_edge, TB>>>(src, dst);

    for (int hop = 0; hop < 2; hop++) {
        k_prep<<<grid_row8, TB>>>(feat, hop);
        k_hopclear<<<grid_clear, TB>>>();
        k_cos<<<grid_edge8, TB>>>(src, dst);   // fused round-1 histogram

        k_resolve<<<1, 256>>>(24);
        k_hist<<<2048, TB>>>(16, 0xFF000000u); k_resolve<<<1, 256>>>(16);
        k_hist<<<2048, TB>>>( 8, 0xFFFF0000u); k_resolve<<<1, 256>>>( 8);
        k_hist<<<2048, TB>>>( 0, 0xFFFFFF00u); k_resolve<<<1, 256>>>( 0);

        k_eq_gather<<<grid_edge, TB>>>();
        k_eq_mark<<<1, 256>>>();

        k_agg<<<grid_row8, TB>>>();
    }

    k_out<<<grid_rowW, TB>>>(W, out);
}